// round 15
// baseline (speedup 1.0000x reference)
#include <cuda_runtime.h>
#include <cuda_bf16.h>
#include <math.h>
#include <stdint.h>

#define TOKENS 8192
#define DIM    4096
#define NEXP   256
#define TOPK   8

#define TM   64
#define BK   32                 // 2 x k16 per chunk
#define NCH  (DIM / BK)         // 128
#define NTH  512

#define ROWB   256              // 8 granules of 32B; granules 0..5 used
#define STAGE  (320 * ROWB)     // rows 0..63 = A, 64..319 = B  (81920 B)
#define SMEM_BYTES (2 * STAGE)  // 163840
#define LGS  264

// pre-split W: [c][n][6 granules x 32B]; granule g = sp*2+cq, words perm (P0,P4,P1,P5,P2,P6,P3,P7)
__device__ __align__(16) char g_ws[NCH * NEXP * 192];
// pre-split X: [t][c][6 granules x 32B]
__device__ __align__(16) char g_xs[(size_t)TOKENS * NCH * 192];

__device__ __forceinline__ void mma_bf16(float* d,
                                         uint32_t a0, uint32_t a1, uint32_t a2, uint32_t a3,
                                         uint32_t b0, uint32_t b1) {
    asm volatile(
        "mma.sync.aligned.m16n8k16.row.col.f32.bf16.bf16.f32 "
        "{%0,%1,%2,%3},{%4,%5,%6,%7},{%8,%9},{%0,%1,%2,%3};"
        : "+f"(d[0]), "+f"(d[1]), "+f"(d[2]), "+f"(d[3])
        : "r"(a0), "r"(a1), "r"(a2), "r"(a3), "r"(b0), "r"(b1));
}

__device__ __forceinline__ uint32_t smem_u32(const void* p) {
    uint32_t a;
    asm("{ .reg .u64 t; cvta.to.shared.u64 t, %1; cvt.u32.u64 %0, t; }" : "=r"(a) : "l"(p));
    return a;
}
#define CP_ASYNC16(dst, src) \
    asm volatile("cp.async.cg.shared.global [%0], [%1], 16;" :: "r"(dst), "l"(src))
#define CP_COMMIT() asm volatile("cp.async.commit_group;" ::: "memory")
#define CP_WAIT0()  asm volatile("cp.async.wait_group 0;" ::: "memory")

// EXACT truncation 3-way split: v = h + m + l bit-exactly
__device__ __forceinline__ void tsplit3(float v, float* h, float* m, float* l) {
    float hh = __uint_as_float(__float_as_uint(v) & 0xFFFF0000u);
    float r  = v - hh;
    float mm = __uint_as_float(__float_as_uint(r) & 0xFFFF0000u);
    *h = hh; *m = mm; *l = r - mm;
}
__device__ __forceinline__ uint32_t packhi(float a, float b) {
    return __byte_perm(__float_as_uint(a), __float_as_uint(b), 0x7632);
}

// XLA logistic: 0.5 + 0.5 * tanh(0.5x)
__device__ __forceinline__ float xla_sigmoid(float v) {
    float x = 0.5f * v;
    float t;
    if (fabsf(x) < 0.0004f) {
        t = x;
    } else {
        float xc = fminf(fmaxf(x, -7.90531110763549805f), 7.90531110763549805f);
        float x2 = xc * xc;
        float p = -2.76076847742355e-16f;
        p = fmaf(p, x2, 2.00018790482477e-13f);
        p = fmaf(p, x2, -8.60467152213735e-11f);
        p = fmaf(p, x2, 5.12229709037114e-08f);
        p = fmaf(p, x2, 1.48572235717979e-05f);
        p = fmaf(p, x2, 6.37261928875436e-04f);
        p = fmaf(p, x2, 4.89352455891786e-03f);
        p = xc * p;
        float q = 1.19825839466702e-06f;
        q = fmaf(q, x2, 1.18534705686654e-04f);
        q = fmaf(q, x2, 2.26843463243900e-03f);
        q = fmaf(q, x2, 4.89352518554385e-03f);
        t = p / q;
    }
    return fmaf(0.5f, t, 0.5f);
}

// ============================================================================
// W prepass (8us, measured)
// ============================================================================
__global__ __launch_bounds__(256) void wsplit_kernel(const float* __restrict__ w) {
    int j = blockIdx.x * 256 + threadIdx.x;   // 32768 = n*128 + c
    int c = j & 127;
    int n = j >> 7;
    const float4* src = (const float4*)(w + (size_t)n * DIM + c * BK);
    float v[32];
    #pragma unroll
    for (int i = 0; i < 8; ++i) {
        float4 f = src[i];
        v[i*4+0] = f.x; v[i*4+1] = f.y; v[i*4+2] = f.z; v[i*4+3] = f.w;
    }
    float H[32], M[32], L[32];
    #pragma unroll
    for (int i = 0; i < 32; ++i) tsplit3(v[i], &H[i], &M[i], &L[i]);

    uint32_t* dst = (uint32_t*)(g_ws + ((size_t)c * NEXP + n) * 192);
    const int perm[8] = {0, 4, 1, 5, 2, 6, 3, 7};
    #pragma unroll
    for (int sp = 0; sp < 3; ++sp) {
        const float* S = (sp == 0) ? H : (sp == 1) ? M : L;
        #pragma unroll
        for (int cq = 0; cq < 2; ++cq) {
            #pragma unroll
            for (int wpos = 0; wpos < 8; ++wpos) {
                int pj = perm[wpos];
                int k0 = cq * 16 + 2 * pj;
                dst[(sp * 2 + cq) * 8 + wpos] = packhi(S[k0], S[k0 + 1]);
            }
        }
    }
}

// ============================================================================
// X prepass v4: 128 tc-blocks per CTA, 4 independent loads/thread (MLP 4)
// grid = 1048576/128 = 8192
// ============================================================================
__global__ __launch_bounds__(256) void xsplit_kernel(const float* __restrict__ x) {
    __shared__ uint32_t sbuf[128 * 48];   // 24 KB
    const int tid = threadIdx.x;
    const size_t tcbase = (size_t)blockIdx.x * 128;

    // 4 independent loads first (MLP 4), then split+stage
    float4 f[4];
    #pragma unroll
    for (int i = 0; i < 4; ++i) {
        int u  = tid + 256 * i;
        f[i] = *(const float4*)(x + (tcbase + (u >> 3)) * 32 + (u & 7) * 4);
    }
    #pragma unroll
    for (int i = 0; i < 4; ++i) {
        int u  = tid + 256 * i;
        int tc = u >> 3;
        int q  = u & 7;
        float H[4], M[4], L[4];
        tsplit3(f[i].x, &H[0], &M[0], &L[0]);
        tsplit3(f[i].y, &H[1], &M[1], &L[1]);
        tsplit3(f[i].z, &H[2], &M[2], &L[2]);
        tsplit3(f[i].w, &H[3], &M[3], &L[3]);
        const int cq = q >> 2;
        const int j0 = (q & 3) * 2;
        const int w0 = (j0 & 3) * 2 + (j0 >> 2);
        const int w1 = ((j0 + 1) & 3) * 2 + ((j0 + 1) >> 2);
        uint32_t* base = sbuf + tc * 48;
        #pragma unroll
        for (int sp = 0; sp < 3; ++sp) {
            const float* S = (sp == 0) ? H : (sp == 1) ? M : L;
            uint32_t* g = base + (sp * 2 + cq) * 8;
            g[w0] = packhi(S[0], S[1]);
            g[w1] = packhi(S[2], S[3]);
        }
    }
    __syncthreads();

    // writeout: 128*192B = 1536 uint4, fully coalesced
    uint4* dst = (uint4*)(g_xs + tcbase * 192);
    const uint4* srcs = (const uint4*)sbuf;
    #pragma unroll
    for (int i = 0; i < 6; ++i)
        dst[tid + 256 * i] = srcs[tid + 256 * i];
}

// ============================================================================
// main kernel: pure cp.async + LDS + MMA (R7/R14 verbatim — measured 245us)
// ============================================================================
__global__ __launch_bounds__(NTH, 1)
void gate_bf16x3_kernel(float* __restrict__ out, int write_idx)
{
    extern __shared__ char smem[];
    const uint32_t sb = smem_u32(smem);
    const int tid    = threadIdx.x;
    const int lane   = tid & 31;
    const int wid    = tid >> 5;
    const int warp_m = wid & 1;
    const int warp_n = wid >> 1;
    const int t0     = blockIdx.x * TM;
    const int fr     = lane >> 2;
    const int fc     = lane & 3;

    float am[2][4][4], ac[2][4][4];
    #pragma unroll
    for (int tm = 0; tm < 2; ++tm)
        #pragma unroll
        for (int tn = 0; tn < 4; ++tn)
            #pragma unroll
            for (int q = 0; q < 4; ++q) { am[tm][tn][q] = 0.f; ac[tm][tn][q] = 0.f; }

    const int uA0  = tid;
    const int rA0  = uA0 / 12;
    const int mA0  = uA0 - rA0 * 12;
    const uint32_t dstA0 = (uint32_t)(rA0 * ROWB + (((mA0 >> 1) ^ (rA0 & 3)) * 32) + (mA0 & 1) * 16);
    const char* srcA0 = g_xs + (size_t)(t0 + rA0) * (NCH * 192) + mA0 * 16;

    const int uA1  = 512 + tid;
    const int rA1  = uA1 / 12;
    const int mA1  = uA1 - rA1 * 12;
    const uint32_t dstA1 = (uint32_t)(rA1 * ROWB + (((mA1 >> 1) ^ (rA1 & 3)) * 32) + (mA1 & 1) * 16);
    const char* srcA1 = g_xs + (size_t)(t0 + rA1) * (NCH * 192) + mA1 * 16;

    uint32_t dstB[6], srcB[6];
    #pragma unroll
    for (int i = 0; i < 6; ++i) {
        int u  = tid + 512 * i;
        int n  = u / 12;
        int mi = u - n * 12;
        int r  = 64 + n;
        dstB[i] = (uint32_t)(r * ROWB + (((mi >> 1) ^ (r & 3)) * 32) + (mi & 1) * 16);
        srcB[i] = (uint32_t)(n * 192 + mi * 16);
    }

    auto issue = [&](int c, int s) {
        const uint32_t sbase = sb + (uint32_t)(s * STAGE);
        const char* wb = g_ws + (size_t)c * (NEXP * 192);
        #pragma unroll
        for (int i = 0; i < 6; ++i)
            CP_ASYNC16(sbase + dstB[i], (const void*)(wb + srcB[i]));
        CP_ASYNC16(sbase + dstA0, (const void*)(srcA0 + (size_t)c * 192));
        if (tid < 256)
            CP_ASYNC16(sbase + dstA1, (const void*)(srcA1 + (size_t)c * 192));
        CP_COMMIT();
    };

    int arow[2][2];
    #pragma unroll
    for (int tm = 0; tm < 2; ++tm) {
        arow[tm][0] = warp_m * 32 + tm * 16 + fr;
        arow[tm][1] = arow[tm][0] + 8;
    }
    int brow[4];
    #pragma unroll
    for (int tn = 0; tn < 4; ++tn) brow[tn] = 64 + warp_n * 32 + tn * 8 + fr;

    issue(0, 0);
    CP_WAIT0();
    __syncthreads();

    for (int c = 0; c < NCH; ++c) {
        const int s = c & 1;
        if (c + 1 < NCH) issue(c + 1, s ^ 1);

        const char* st = smem + s * STAGE;
        #pragma unroll
        for (int cq = 0; cq < 2; ++cq) {
            uint2 A[3][2][2];
            #pragma unroll
            for (int tm = 0; tm < 2; ++tm)
                #pragma unroll
                for (int hf = 0; hf < 2; ++hf) {
                    int r = arow[tm][hf];
                    const char* pr = st + r * ROWB;
                    const int rx = r & 3;
                    A[0][tm][hf] = *(const uint2*)(pr + (((0 * 2 + cq) ^ rx) * 32) + fc * 8);
                    A[1][tm][hf] = *(const uint2*)(pr + (((1 * 2 + cq) ^ rx) * 32) + fc * 8);
                    A[2][tm][hf] = *(const uint2*)(pr + (((2 * 2 + cq) ^ rx) * 32) + fc * 8);
                }
            #pragma unroll
            for (int tn = 0; tn < 4; ++tn) {
                int r = brow[tn];
                const char* pr = st + r * ROWB;
                const int rx = r & 3;
                uint2 bh = *(const uint2*)(pr + (((0 * 2 + cq) ^ rx) * 32) + fc * 8);
                uint2 bm = *(const uint2*)(pr + (((1 * 2 + cq) ^ rx) * 32) + fc * 8);
                uint2 bl = *(const uint2*)(pr + (((2 * 2 + cq) ^ rx) * 32) + fc * 8);
                #pragma unroll
                for (int tm = 0; tm < 2; ++tm) {
                    float* dm = am[tm][tn];
                    float* dc = ac[tm][tn];
                    uint2 ah0 = A[0][tm][0], ah1 = A[0][tm][1];
                    uint2 am0 = A[1][tm][0], am1 = A[1][tm][1];
                    uint2 al0 = A[2][tm][0], al1 = A[2][tm][1];
                    mma_bf16(dm, ah0.x, ah1.x, ah0.y, ah1.y, bh.x, bh.y);  // hh
                    mma_bf16(dc, ah0.x, ah1.x, ah0.y, ah1.y, bm.x, bm.y);  // hm
                    mma_bf16(dc, am0.x, am1.x, am0.y, am1.y, bh.x, bh.y);  // mh
                    mma_bf16(dc, am0.x, am1.x, am0.y, am1.y, bm.x, bm.y);  // mm
                    mma_bf16(dc, ah0.x, ah1.x, ah0.y, ah1.y, bl.x, bl.y);  // hl
                    mma_bf16(dc, al0.x, al1.x, al0.y, al1.y, bh.x, bh.y);  // lh
                }
            }
        }

        CP_WAIT0();
        __syncthreads();
    }

    // epilogue: logits -> smem [64][LGS]
    float* lg = (float*)smem;
    #pragma unroll
    for (int tm = 0; tm < 2; ++tm) {
        int r = warp_m * 32 + tm * 16 + fr;
        #pragma unroll
        for (int tn = 0; tn < 4; ++tn) {
            int cc = warp_n * 32 + tn * 8 + fc * 2;
            float v0 = am[tm][tn][0] + ac[tm][tn][0];
            float v1 = am[tm][tn][1] + ac[tm][tn][1];
            float v2 = am[tm][tn][2] + ac[tm][tn][2];
            float v3 = am[tm][tn][3] + ac[tm][tn][3];
            *(float2*)(lg + (size_t)r * LGS + cc)       = make_float2(v0, v1);
            *(float2*)(lg + (size_t)(r + 8) * LGS + cc) = make_float2(v2, v3);
        }
    }
    __syncthreads();

    // top-8 on sigmoid scores, lower-index tie-break
    #pragma unroll
    for (int it = 0; it < 4; ++it) {
        const int t = wid * 4 + it;
        float v[8];
        #pragma unroll
        for (int j = 0; j < 8; ++j)
            v[j] = xla_sigmoid(lg[(size_t)t * LGS + lane + j * 32]);

        float topv[8];
        int   topi[8];
        unsigned used = 0;

        #pragma unroll
        for (int r = 0; r < 8; ++r) {
            float best = -INFINITY;
            int   bidx = 0x7fffffff;
            #pragma unroll
            for (int j = 0; j < 8; ++j) {
                if (!((used >> j) & 1u)) {
                    float val = v[j];
                    int   id  = lane + j * 32;
                    if (val > best || (val == best && id < bidx)) { best = val; bidx = id; }
                }
            }
            #pragma unroll
            for (int off = 16; off > 0; off >>= 1) {
                float ov = __shfl_xor_sync(0xffffffffu, best, off);
                int   oi = __shfl_xor_sync(0xffffffffu, bidx, off);
                if (ov > best || (ov == best && oi < bidx)) { best = ov; bidx = oi; }
            }
            topv[r] = best;
            topi[r] = bidx;
            if ((bidx & 31) == lane) used |= 1u << (bidx >> 5);
        }

        float sum = 0.f;
        #pragma unroll
        for (int r = 0; r < 8; ++r) sum += topv[r];
        float inv = 1.f / sum;

        if (lane == 0) {
            int gt = t0 + t;
            #pragma unroll
            for (int r = 0; r < 8; ++r)
                out[(size_t)gt * TOPK + r] = topv[r] * inv;
            if (write_idx) {
                #pragma unroll
                for (int r = 0; r < 8; ++r)
                    out[(size_t)TOKENS * TOPK + (size_t)gt * TOPK + r] = (float)topi[r];
            }
        }
    }
}

extern "C" void kernel_launch(void* const* d_in, const int* in_sizes, int n_in,
                              void* d_out, int out_size)
{
    const float* x = (const float*)d_in[0];   // [TOKENS, DIM]
    const float* w = (const float*)d_in[1];   // [NEXP, DIM]
    float* out = (float*)d_out;

    int write_idx = (out_size >= 2 * TOKENS * TOPK) ? 1 : 0;

    cudaFuncSetAttribute(gate_bf16x3_kernel, cudaFuncAttributeMaxDynamicSharedMemorySize, SMEM_BYTES);

    wsplit_kernel<<<(NEXP * NCH) / 256, 256>>>(w);
    xsplit_kernel<<<(TOKENS * NCH) / 128, 256>>>(x);
    gate_bf16x3_kernel<<<TOKENS / TM, NTH, SMEM_BYTES>>>(out, write_idx);
}

// round 16
// speedup vs baseline: 1.1926x; 1.1926x over previous
#include <cuda_runtime.h>
#include <cuda_bf16.h>
#include <math.h>
#include <stdint.h>

#define TOKENS 8192
#define DIM    4096
#define NEXP   256
#define TOPK   8

#define TM   64
#define BK   32                 // 2 x k16 per chunk
#define NCH  (DIM / BK)         // 128
#define NTH  512

// Row layout: 16 slots x 16B = 256B. Slot s = sp*4 + cq*2 + half (0..11 used).
// Slot content: 8 bf16, plain k order (k = cq*16 + half*8 + 0..7).
// Swizzle: byte = row*256 + ((s ^ (row&7)) << 4).
#define ROWB   256
#define STAGE  (320 * ROWB)     // rows 0..63 = A (tokens), 64..319 = B (experts)
#define SMEM_BYTES (2 * STAGE)  // 163840
#define LGS  264

// pre-split W: [c][n][12 slots x 16B] plain-k slot layout
__device__ __align__(16) char g_ws[NCH * NEXP * 192];

__device__ __forceinline__ void mma_bf16(float* d,
                                         uint32_t a0, uint32_t a1, uint32_t a2, uint32_t a3,
                                         uint32_t b0, uint32_t b1) {
    asm volatile(
        "mma.sync.aligned.m16n8k16.row.col.f32.bf16.bf16.f32 "
        "{%0,%1,%2,%3},{%4,%5,%6,%7},{%8,%9},{%0,%1,%2,%3};"
        : "+f"(d[0]), "+f"(d[1]), "+f"(d[2]), "+f"(d[3])
        : "r"(a0), "r"(a1), "r"(a2), "r"(a3), "r"(b0), "r"(b1));
}

__device__ __forceinline__ void ldsm4(uint32_t* r, uint32_t addr) {
    asm volatile("ldmatrix.sync.aligned.m8n8.x4.shared.b16 {%0,%1,%2,%3}, [%4];"
                 : "=r"(r[0]), "=r"(r[1]), "=r"(r[2]), "=r"(r[3]) : "r"(addr));
}

__device__ __forceinline__ uint32_t smem_u32(const void* p) {
    uint32_t a;
    asm("{ .reg .u64 t; cvta.to.shared.u64 t, %1; cvt.u32.u64 %0, t; }" : "=r"(a) : "l"(p));
    return a;
}
#define CP_ASYNC16(dst, src) \
    asm volatile("cp.async.cg.shared.global [%0], [%1], 16;" :: "r"(dst), "l"(src))
#define CP_COMMIT() asm volatile("cp.async.commit_group;" ::: "memory")
#define CP_WAIT0()  asm volatile("cp.async.wait_group 0;" ::: "memory")

// EXACT truncation 3-way split: v = h + m + l bit-exactly
__device__ __forceinline__ void tsplit3(float v, float* h, float* m, float* l) {
    float hh = __uint_as_float(__float_as_uint(v) & 0xFFFF0000u);
    float r  = v - hh;
    float mm = __uint_as_float(__float_as_uint(r) & 0xFFFF0000u);
    *h = hh; *m = mm; *l = r - mm;
}
__device__ __forceinline__ uint32_t packhi(float a, float b) {
    return __byte_perm(__float_as_uint(a), __float_as_uint(b), 0x7632);
}

// XLA logistic: 0.5 + 0.5 * tanh(0.5x)
__device__ __forceinline__ float xla_sigmoid(float v) {
    float x = 0.5f * v;
    float t;
    if (fabsf(x) < 0.0004f) {
        t = x;
    } else {
        float xc = fminf(fmaxf(x, -7.90531110763549805f), 7.90531110763549805f);
        float x2 = xc * xc;
        float p = -2.76076847742355e-16f;
        p = fmaf(p, x2, 2.00018790482477e-13f);
        p = fmaf(p, x2, -8.60467152213735e-11f);
        p = fmaf(p, x2, 5.12229709037114e-08f);
        p = fmaf(p, x2, 1.48572235717979e-05f);
        p = fmaf(p, x2, 6.37261928875436e-04f);
        p = fmaf(p, x2, 4.89352455891786e-03f);
        p = xc * p;
        float q = 1.19825839466702e-06f;
        q = fmaf(q, x2, 1.18534705686654e-04f);
        q = fmaf(q, x2, 2.26843463243900e-03f);
        q = fmaf(q, x2, 4.89352518554385e-03f);
        t = p / q;
    }
    return fmaf(0.5f, t, 0.5f);
}

// ============================================================================
// W prepass: truncation split into plain-k slot layout [c][n][12x16B]
// ============================================================================
__global__ __launch_bounds__(256) void wsplit_kernel(const float* __restrict__ w) {
    int j = blockIdx.x * 256 + threadIdx.x;   // 32768 = n*128 + c
    int c = j & 127;
    int n = j >> 7;
    const float4* src = (const float4*)(w + (size_t)n * DIM + c * BK);
    float v[32];
    #pragma unroll
    for (int i = 0; i < 8; ++i) {
        float4 f = src[i];
        v[i*4+0] = f.x; v[i*4+1] = f.y; v[i*4+2] = f.z; v[i*4+3] = f.w;
    }
    float H[32], M[32], L[32];
    #pragma unroll
    for (int i = 0; i < 32; ++i) tsplit3(v[i], &H[i], &M[i], &L[i]);

    uint32_t* dst = (uint32_t*)(g_ws + ((size_t)c * NEXP + n) * 192);
    #pragma unroll
    for (int s = 0; s < 12; ++s) {
        int sp = s >> 2, cq = (s >> 1) & 1, hf = s & 1;
        const float* S = (sp == 0) ? H : (sp == 1) ? M : L;
        int k0 = cq * 16 + hf * 8;
        #pragma unroll
        for (int jj = 0; jj < 4; ++jj)
            dst[s * 4 + jj] = packhi(S[k0 + 2 * jj], S[k0 + 2 * jj + 1]);
    }
}

// ============================================================================
// main kernel: fused, ldmatrix fragment loads
// ============================================================================
__global__ __launch_bounds__(NTH, 1)
void gate_bf16x3_kernel(const float* __restrict__ x,
                        float* __restrict__ out,
                        int write_idx)
{
    extern __shared__ char smem[];
    const uint32_t sb = smem_u32(smem);
    const int tid    = threadIdx.x;
    const int lane   = tid & 31;
    const int wid    = tid >> 5;
    const int warp_m = wid & 1;      // 2 x 32 tokens
    const int warp_n = wid >> 1;     // 8 x 32 experts
    const int t0     = blockIdx.x * TM;

    float dm[2][4][4], dc[2][4][4];
    #pragma unroll
    for (int tm = 0; tm < 2; ++tm)
        #pragma unroll
        for (int tn = 0; tn < 4; ++tn)
            #pragma unroll
            for (int q = 0; q < 4; ++q) { dm[tm][tn][q] = 0.f; dc[tm][tn][q] = 0.f; }

    // ---- LDSM addressing (rx = lane&7 holds for every fragment row) ----
    const uint32_t rx = lane & 7;
    const int ahalf = lane >> 4;                         // 0: k0-7, 1: k8-15
    uint32_t abase[2];
    #pragma unroll
    for (int tm = 0; tm < 2; ++tm)
        abase[tm] = (uint32_t)((warp_m * 32 + tm * 16 + ((lane >> 3) & 1) * 8 + (lane & 7)) * ROWB);
    const uint32_t bbase = (uint32_t)((64 + warp_n * 32 + (lane >> 3) * 8 + (lane & 7)) * ROWB);

    // ---- W staging via cp.async: 3072 slot-units; u = tid + 512*i ----
    uint32_t dstB[6], srcB[6];
    #pragma unroll
    for (int i = 0; i < 6; ++i) {
        int u  = tid + 512 * i;
        int n  = u / 12;
        int mi = u - n * 12;
        dstB[i] = (uint32_t)((64 + n) * ROWB + ((mi ^ (n & 7)) << 4));
        srcB[i] = (uint32_t)(n * 192 + mi * 16);
    }

    // ---- x staging: thread -> row xr = tid>>3, q = tid&7 (4 k at q*4) ----
    const int xr  = tid >> 3;
    const int xq  = tid & 7;
    const int xcq = xq >> 2;
    const int xhf = (xq >> 1) & 1;
    const int xoff = (xq & 1) * 8;
    const int xrx = xr & 7;
    const float* xsrc = x + (size_t)(t0 + xr) * DIM + xq * 4;

    float4 ra;

    auto issue = [&](int c, int s) {
        const uint32_t sbase = sb + (uint32_t)(s * STAGE);
        const char* wb = g_ws + (size_t)c * (NEXP * 192);
        #pragma unroll
        for (int i = 0; i < 6; ++i)
            CP_ASYNC16(sbase + dstB[i], (const void*)(wb + srcB[i]));
        CP_COMMIT();
        ra = *(const float4*)(xsrc + (size_t)c * BK);
    };

    auto finish_x = [&](int s) {
        float H[4], M[4], L[4];
        tsplit3(ra.x, &H[0], &M[0], &L[0]);
        tsplit3(ra.y, &H[1], &M[1], &L[1]);
        tsplit3(ra.z, &H[2], &M[2], &L[2]);
        tsplit3(ra.w, &H[3], &M[3], &L[3]);
        char* base = smem + s * STAGE + xr * ROWB;
        #pragma unroll
        for (int sp = 0; sp < 3; ++sp) {
            const float* S = (sp == 0) ? H : (sp == 1) ? M : L;
            int slot = sp * 4 + xcq * 2 + xhf;
            *(uint2*)(base + ((slot ^ xrx) << 4) + xoff) =
                make_uint2(packhi(S[0], S[1]), packhi(S[2], S[3]));
        }
    };

    // prologue
    issue(0, 0);
    finish_x(0);
    CP_WAIT0();
    __syncthreads();

    for (int c = 0; c < NCH; ++c) {
        const int s = c & 1;
        if (c + 1 < NCH) issue(c + 1, s ^ 1);

        const uint32_t stb = sb + (uint32_t)(s * STAGE);
        #pragma unroll
        for (int cq = 0; cq < 2; ++cq) {
            // A fragments: slot = sp*4 + cq*2 + ahalf
            uint32_t Ah[2][4], Am[2][4], Al[2][4];
            #pragma unroll
            for (int tm = 0; tm < 2; ++tm) {
                uint32_t ab = stb + abase[tm];
                ldsm4(Ah[tm], ab + (((0 * 4 + cq * 2 + ahalf) ^ rx) << 4));
                ldsm4(Am[tm], ab + (((1 * 4 + cq * 2 + ahalf) ^ rx) << 4));
                ldsm4(Al[tm], ab + (((2 * 4 + cq * 2 + ahalf) ^ rx) << 4));
            }
            // B fragments: half explicit; x4 covers tn=0..3
            uint32_t Bh0[4], Bh1[4], Bm0[4], Bm1[4], Bl0[4], Bl1[4];
            {
                uint32_t bb = stb + bbase;
                ldsm4(Bh0, bb + (((0 * 4 + cq * 2 + 0) ^ rx) << 4));
                ldsm4(Bh1, bb + (((0 * 4 + cq * 2 + 1) ^ rx) << 4));
                ldsm4(Bm0, bb + (((1 * 4 + cq * 2 + 0) ^ rx) << 4));
                ldsm4(Bm1, bb + (((1 * 4 + cq * 2 + 1) ^ rx) << 4));
                ldsm4(Bl0, bb + (((2 * 4 + cq * 2 + 0) ^ rx) << 4));
                ldsm4(Bl1, bb + (((2 * 4 + cq * 2 + 1) ^ rx) << 4));
            }
            #pragma unroll
            for (int tn = 0; tn < 4; ++tn) {
                #pragma unroll
                for (int tm = 0; tm < 2; ++tm) {
                    float* pm = dm[tm][tn];
                    float* pc = dc[tm][tn];
                    mma_bf16(pm, Ah[tm][0], Ah[tm][1], Ah[tm][2], Ah[tm][3], Bh0[tn], Bh1[tn]); // hh
                    mma_bf16(pc, Ah[tm][0], Ah[tm][1], Ah[tm][2], Ah[tm][3], Bm0[tn], Bm1[tn]); // hm
                    mma_bf16(pc, Am[tm][0], Am[tm][1], Am[tm][2], Am[tm][3], Bh0[tn], Bh1[tn]); // mh
                    mma_bf16(pc, Am[tm][0], Am[tm][1], Am[tm][2], Am[tm][3], Bm0[tn], Bm1[tn]); // mm
                    mma_bf16(pc, Ah[tm][0], Ah[tm][1], Ah[tm][2], Ah[tm][3], Bl0[tn], Bl1[tn]); // hl
                    mma_bf16(pc, Al[tm][0], Al[tm][1], Al[tm][2], Al[tm][3], Bh0[tn], Bh1[tn]); // lh
                }
            }
        }

        if (c + 1 < NCH) finish_x(s ^ 1);
        CP_WAIT0();
        __syncthreads();
    }

    // epilogue: logits -> smem [64][LGS]; mma fragment rows: fr = lane>>2, fc = lane&3
    const int fr = lane >> 2;
    const int fc = lane & 3;
    float* lg = (float*)smem;
    #pragma unroll
    for (int tm = 0; tm < 2; ++tm) {
        int r = warp_m * 32 + tm * 16 + fr;
        #pragma unroll
        for (int tn = 0; tn < 4; ++tn) {
            int cc = warp_n * 32 + tn * 8 + fc * 2;
            float v0 = dm[tm][tn][0] + dc[tm][tn][0];
            float v1 = dm[tm][tn][1] + dc[tm][tn][1];
            float v2 = dm[tm][tn][2] + dc[tm][tn][2];
            float v3 = dm[tm][tn][3] + dc[tm][tn][3];
            *(float2*)(lg + (size_t)r * LGS + cc)       = make_float2(v0, v1);
            *(float2*)(lg + (size_t)(r + 8) * LGS + cc) = make_float2(v2, v3);
        }
    }
    __syncthreads();

    // top-8 on sigmoid scores, lower-index tie-break
    #pragma unroll
    for (int it = 0; it < 4; ++it) {
        const int t = wid * 4 + it;
        float v[8];
        #pragma unroll
        for (int j = 0; j < 8; ++j)
            v[j] = xla_sigmoid(lg[(size_t)t * LGS + lane + j * 32]);

        float topv[8];
        int   topi[8];
        unsigned used = 0;

        #pragma unroll
        for (int r = 0; r < 8; ++r) {
            float best = -INFINITY;
            int   bidx = 0x7fffffff;
            #pragma unroll
            for (int j = 0; j < 8; ++j) {
                if (!((used >> j) & 1u)) {
                    float val = v[j];
                    int   id  = lane + j * 32;
                    if (val > best || (val == best && id < bidx)) { best = val; bidx = id; }
                }
            }
            #pragma unroll
            for (int off = 16; off > 0; off >>= 1) {
                float ov = __shfl_xor_sync(0xffffffffu, best, off);
                int   oi = __shfl_xor_sync(0xffffffffu, bidx, off);
                if (ov > best || (ov == best && oi < bidx)) { best = ov; bidx = oi; }
            }
            topv[r] = best;
            topi[r] = bidx;
            if ((bidx & 31) == lane) used |= 1u << (bidx >> 5);
        }

        float sum = 0.f;
        #pragma unroll
        for (int r = 0; r < 8; ++r) sum += topv[r];
        float inv = 1.f / sum;

        if (lane == 0) {
            int gt = t0 + t;
            #pragma unroll
            for (int r = 0; r < 8; ++r)
                out[(size_t)gt * TOPK + r] = topv[r] * inv;
            if (write_idx) {
                #pragma unroll
                for (int r = 0; r < 8; ++r)
                    out[(size_t)TOKENS * TOPK + (size_t)gt * TOPK + r] = (float)topi[r];
            }
        }
    }
}

extern "C" void kernel_launch(void* const* d_in, const int* in_sizes, int n_in,
                              void* d_out, int out_size)
{
    const float* x = (const float*)d_in[0];   // [TOKENS, DIM]
    const float* w = (const float*)d_in[1];   // [NEXP, DIM]
    float* out = (float*)d_out;

    int write_idx = (out_size >= 2 * TOKENS * TOPK) ? 1 : 0;

    cudaFuncSetAttribute(gate_bf16x3_kernel, cudaFuncAttributeMaxDynamicSharedMemorySize, SMEM_BYTES);

    wsplit_kernel<<<(NEXP * NCH) / 256, 256>>>(w);
    gate_bf16x3_kernel<<<TOKENS / TM, NTH, SMEM_BYTES>>>(x, out, write_idx);
}

// round 17
// speedup vs baseline: 1.2049x; 1.0103x over previous
#include <cuda_runtime.h>
#include <cuda_bf16.h>
#include <math.h>
#include <stdint.h>

#define TOKENS 8192
#define DIM    4096
#define NEXP   256
#define TOPK   8

#define TM   64
#define BK   32                 // 2 x k16 per chunk
#define NCH  (DIM / BK)         // 128
#define NTH  512

// Row layout: 16 slots x 16B = 256B. Slot s = sp*4 + cq*2 + half (0..11 used).
// Swizzle: byte = row*256 + ((s ^ (row&7)) << 4).
#define ROWB   256
#define STAGE  (320 * ROWB)     // rows 0..63 = A (tokens), 64..319 = B (experts)
#define SMEM_BYTES (2 * STAGE)  // 163840
#define LGS  264

// pre-split W: [c][n][12 slots x 16B] plain-k slot layout
__device__ __align__(16) char g_ws[NCH * NEXP * 192];

__device__ __forceinline__ void mma_bf16(float* d,
                                         uint32_t a0, uint32_t a1, uint32_t a2, uint32_t a3,
                                         uint32_t b0, uint32_t b1) {
    asm volatile(
        "mma.sync.aligned.m16n8k16.row.col.f32.bf16.bf16.f32 "
        "{%0,%1,%2,%3},{%4,%5,%6,%7},{%8,%9},{%0,%1,%2,%3};"
        : "+f"(d[0]), "+f"(d[1]), "+f"(d[2]), "+f"(d[3])
        : "r"(a0), "r"(a1), "r"(a2), "r"(a3), "r"(b0), "r"(b1));
}

__device__ __forceinline__ void ldsm4(uint32_t* r, uint32_t addr) {
    asm volatile("ldmatrix.sync.aligned.m8n8.x4.shared.b16 {%0,%1,%2,%3}, [%4];"
                 : "=r"(r[0]), "=r"(r[1]), "=r"(r[2]), "=r"(r[3]) : "r"(addr));
}

__device__ __forceinline__ uint32_t smem_u32(const void* p) {
    uint32_t a;
    asm("{ .reg .u64 t; cvta.to.shared.u64 t, %1; cvt.u32.u64 %0, t; }" : "=r"(a) : "l"(p));
    return a;
}
#define CP_ASYNC16(dst, src) \
    asm volatile("cp.async.cg.shared.global [%0], [%1], 16;" :: "r"(dst), "l"(src))
#define CP_COMMIT() asm volatile("cp.async.commit_group;" ::: "memory")
#define CP_WAIT0()  asm volatile("cp.async.wait_group 0;" ::: "memory")

// EXACT truncation 3-way split: v = h + m + l bit-exactly
__device__ __forceinline__ void tsplit3(float v, float* h, float* m, float* l) {
    float hh = __uint_as_float(__float_as_uint(v) & 0xFFFF0000u);
    float r  = v - hh;
    float mm = __uint_as_float(__float_as_uint(r) & 0xFFFF0000u);
    *h = hh; *m = mm; *l = r - mm;
}
__device__ __forceinline__ uint32_t packhi(float a, float b) {
    return __byte_perm(__float_as_uint(a), __float_as_uint(b), 0x7632);
}

// XLA logistic: 0.5 + 0.5 * tanh(0.5x)
__device__ __forceinline__ float xla_sigmoid(float v) {
    float x = 0.5f * v;
    float t;
    if (fabsf(x) < 0.0004f) {
        t = x;
    } else {
        float xc = fminf(fmaxf(x, -7.90531110763549805f), 7.90531110763549805f);
        float x2 = xc * xc;
        float p = -2.76076847742355e-16f;
        p = fmaf(p, x2, 2.00018790482477e-13f);
        p = fmaf(p, x2, -8.60467152213735e-11f);
        p = fmaf(p, x2, 5.12229709037114e-08f);
        p = fmaf(p, x2, 1.48572235717979e-05f);
        p = fmaf(p, x2, 6.37261928875436e-04f);
        p = fmaf(p, x2, 4.89352455891786e-03f);
        p = xc * p;
        float q = 1.19825839466702e-06f;
        q = fmaf(q, x2, 1.18534705686654e-04f);
        q = fmaf(q, x2, 2.26843463243900e-03f);
        q = fmaf(q, x2, 4.89352518554385e-03f);
        t = p / q;
    }
    return fmaf(0.5f, t, 0.5f);
}

// ============================================================================
// W prepass: truncation split into plain-k slot layout [c][n][12x16B]
// ============================================================================
__global__ __launch_bounds__(256) void wsplit_kernel(const float* __restrict__ w) {
    int j = blockIdx.x * 256 + threadIdx.x;   // 32768 = n*128 + c
    int c = j & 127;
    int n = j >> 7;
    const float4* src = (const float4*)(w + (size_t)n * DIM + c * BK);
    float v[32];
    #pragma unroll
    for (int i = 0; i < 8; ++i) {
        float4 f = src[i];
        v[i*4+0] = f.x; v[i*4+1] = f.y; v[i*4+2] = f.z; v[i*4+3] = f.w;
    }
    float H[32], M[32], L[32];
    #pragma unroll
    for (int i = 0; i < 32; ++i) tsplit3(v[i], &H[i], &M[i], &L[i]);

    uint32_t* dst = (uint32_t*)(g_ws + ((size_t)c * NEXP + n) * 192);
    #pragma unroll
    for (int s = 0; s < 12; ++s) {
        int sp = s >> 2, cq = (s >> 1) & 1, hf = s & 1;
        const float* S = (sp == 0) ? H : (sp == 1) ? M : L;
        int k0 = cq * 16 + hf * 8;
        #pragma unroll
        for (int jj = 0; jj < 4; ++jj)
            dst[s * 4 + jj] = packhi(S[k0 + 2 * jj], S[k0 + 2 * jj + 1]);
    }
}

// ============================================================================
// main kernel: fused, ldmatrix loads, TERM-MAJOR MMA order (RAW-chain free)
// ============================================================================
__global__ __launch_bounds__(NTH, 1)
void gate_bf16x3_kernel(const float* __restrict__ x,
                        float* __restrict__ out,
                        int write_idx)
{
    extern __shared__ char smem[];
    const uint32_t sb = smem_u32(smem);
    const int tid    = threadIdx.x;
    const int lane   = tid & 31;
    const int wid    = tid >> 5;
    const int warp_m = wid & 1;      // 2 x 32 tokens
    const int warp_n = wid >> 1;     // 8 x 32 experts
    const int t0     = blockIdx.x * TM;

    float dm[2][4][4], dc[2][4][4];
    #pragma unroll
    for (int tm = 0; tm < 2; ++tm)
        #pragma unroll
        for (int tn = 0; tn < 4; ++tn)
            #pragma unroll
            for (int q = 0; q < 4; ++q) { dm[tm][tn][q] = 0.f; dc[tm][tn][q] = 0.f; }

    // ---- LDSM addressing ----
    const uint32_t rx = lane & 7;
    const int ahalf = lane >> 4;
    uint32_t abase[2];
    #pragma unroll
    for (int tm = 0; tm < 2; ++tm)
        abase[tm] = (uint32_t)((warp_m * 32 + tm * 16 + ((lane >> 3) & 1) * 8 + (lane & 7)) * ROWB);
    const uint32_t bbase = (uint32_t)((64 + warp_n * 32 + (lane >> 3) * 8 + (lane & 7)) * ROWB);

    // ---- W staging via cp.async ----
    uint32_t dstB[6], srcB[6];
    #pragma unroll
    for (int i = 0; i < 6; ++i) {
        int u  = tid + 512 * i;
        int n  = u / 12;
        int mi = u - n * 12;
        dstB[i] = (uint32_t)((64 + n) * ROWB + ((mi ^ (n & 7)) << 4));
        srcB[i] = (uint32_t)(n * 192 + mi * 16);
    }

    // ---- x staging ----
    const int xr  = tid >> 3;
    const int xq  = tid & 7;
    const int xcq = xq >> 2;
    const int xhf = (xq >> 1) & 1;
    const int xoff = (xq & 1) * 8;
    const int xrx = xr & 7;
    const float* xsrc = x + (size_t)(t0 + xr) * DIM + xq * 4;

    float4 ra;

    auto issue = [&](int c, int s) {
        const uint32_t sbase = sb + (uint32_t)(s * STAGE);
        const char* wb = g_ws + (size_t)c * (NEXP * 192);
        #pragma unroll
        for (int i = 0; i < 6; ++i)
            CP_ASYNC16(sbase + dstB[i], (const void*)(wb + srcB[i]));
        CP_COMMIT();
        ra = *(const float4*)(xsrc + (size_t)c * BK);
    };

    auto finish_x = [&](int s) {
        float H[4], M[4], L[4];
        tsplit3(ra.x, &H[0], &M[0], &L[0]);
        tsplit3(ra.y, &H[1], &M[1], &L[1]);
        tsplit3(ra.z, &H[2], &M[2], &L[2]);
        tsplit3(ra.w, &H[3], &M[3], &L[3]);
        char* base = smem + s * STAGE + xr * ROWB;
        #pragma unroll
        for (int sp = 0; sp < 3; ++sp) {
            const float* S = (sp == 0) ? H : (sp == 1) ? M : L;
            int slot = sp * 4 + xcq * 2 + xhf;
            *(uint2*)(base + ((slot ^ xrx) << 4) + xoff) =
                make_uint2(packhi(S[0], S[1]), packhi(S[2], S[3]));
        }
    };

    // prologue
    issue(0, 0);
    finish_x(0);
    CP_WAIT0();
    __syncthreads();

    for (int c = 0; c < NCH; ++c) {
        const int s = c & 1;
        if (c + 1 < NCH) issue(c + 1, s ^ 1);

        const uint32_t stb = sb + (uint32_t)(s * STAGE);
        #pragma unroll
        for (int cq = 0; cq < 2; ++cq) {
            uint32_t Ah[2][4], Am[2][4], Al[2][4];
            #pragma unroll
            for (int tm = 0; tm < 2; ++tm) {
                uint32_t ab = stb + abase[tm];
                ldsm4(Ah[tm], ab + (((0 * 4 + cq * 2 + ahalf) ^ rx) << 4));
                ldsm4(Am[tm], ab + (((1 * 4 + cq * 2 + ahalf) ^ rx) << 4));
                ldsm4(Al[tm], ab + (((2 * 4 + cq * 2 + ahalf) ^ rx) << 4));
            }
            uint32_t Bh0[4], Bh1[4], Bm0[4], Bm1[4], Bl0[4], Bl1[4];
            {
                uint32_t bb = stb + bbase;
                ldsm4(Bh0, bb + (((0 * 4 + cq * 2 + 0) ^ rx) << 4));
                ldsm4(Bh1, bb + (((0 * 4 + cq * 2 + 1) ^ rx) << 4));
                ldsm4(Bm0, bb + (((1 * 4 + cq * 2 + 0) ^ rx) << 4));
                ldsm4(Bm1, bb + (((1 * 4 + cq * 2 + 1) ^ rx) << 4));
                ldsm4(Bl0, bb + (((2 * 4 + cq * 2 + 0) ^ rx) << 4));
                ldsm4(Bl1, bb + (((2 * 4 + cq * 2 + 1) ^ rx) << 4));
            }
            // ---- TERM-MAJOR: 8 independent accumulators between reuses ----
            #pragma unroll
            for (int tn = 0; tn < 4; ++tn)   // hh -> dm
                #pragma unroll
                for (int tm = 0; tm < 2; ++tm)
                    mma_bf16(dm[tm][tn], Ah[tm][0], Ah[tm][1], Ah[tm][2], Ah[tm][3], Bh0[tn], Bh1[tn]);
            #pragma unroll
            for (int tn = 0; tn < 4; ++tn)   // hm -> dc
                #pragma unroll
                for (int tm = 0; tm < 2; ++tm)
                    mma_bf16(dc[tm][tn], Ah[tm][0], Ah[tm][1], Ah[tm][2], Ah[tm][3], Bm0[tn], Bm1[tn]);
            #pragma unroll
            for (int tn = 0; tn < 4; ++tn)   // mh -> dc
                #pragma unroll
                for (int tm = 0; tm < 2; ++tm)
                    mma_bf16(dc[tm][tn], Am[tm][0], Am[tm][1], Am[tm][2], Am[tm][3], Bh0[tn], Bh1[tn]);
            #pragma unroll
            for (int tn = 0; tn < 4; ++tn)   // mm -> dc
                #pragma unroll
                for (int tm = 0; tm < 2; ++tm)
                    mma_bf16(dc[tm][tn], Am[tm][0], Am[tm][1], Am[tm][2], Am[tm][3], Bm0[tn], Bm1[tn]);
            #pragma unroll
            for (int tn = 0; tn < 4; ++tn)   // hl -> dc
                #pragma unroll
                for (int tm = 0; tm < 2; ++tm)
                    mma_bf16(dc[tm][tn], Ah[tm][0], Ah[tm][1], Ah[tm][2], Ah[tm][3], Bl0[tn], Bl1[tn]);
            #pragma unroll
            for (int tn = 0; tn < 4; ++tn)   // lh -> dc
                #pragma unroll
                for (int tm = 0; tm < 2; ++tm)
                    mma_bf16(dc[tm][tn], Al[tm][0], Al[tm][1], Al[tm][2], Al[tm][3], Bh0[tn], Bh1[tn]);
        }

        if (c + 1 < NCH) finish_x(s ^ 1);
        CP_WAIT0();
        __syncthreads();
    }

    // epilogue: logits -> smem [64][LGS]
    const int fr = lane >> 2;
    const int fc = lane & 3;
    float* lg = (float*)smem;
    #pragma unroll
    for (int tm = 0; tm < 2; ++tm) {
        int r = warp_m * 32 + tm * 16 + fr;
        #pragma unroll
        for (int tn = 0; tn < 4; ++tn) {
            int cc = warp_n * 32 + tn * 8 + fc * 2;
            float v0 = dm[tm][tn][0] + dc[tm][tn][0];
            float v1 = dm[tm][tn][1] + dc[tm][tn][1];
            float v2 = dm[tm][tn][2] + dc[tm][tn][2];
            float v3 = dm[tm][tn][3] + dc[tm][tn][3];
            *(float2*)(lg + (size_t)r * LGS + cc)       = make_float2(v0, v1);
            *(float2*)(lg + (size_t)(r + 8) * LGS + cc) = make_float2(v2, v3);
        }
    }
    __syncthreads();

    // top-8 on sigmoid scores, lower-index tie-break
    #pragma unroll
    for (int it = 0; it < 4; ++it) {
        const int t = wid * 4 + it;
        float v[8];
        #pragma unroll
        for (int j = 0; j < 8; ++j)
            v[j] = xla_sigmoid(lg[(size_t)t * LGS + lane + j * 32]);

        float topv[8];
        int   topi[8];
        unsigned used = 0;

        #pragma unroll
        for (int r = 0; r < 8; ++r) {
            float best = -INFINITY;
            int   bidx = 0x7fffffff;
            #pragma unroll
            for (int j = 0; j < 8; ++j) {
                if (!((used >> j) & 1u)) {
                    float val = v[j];
                    int   id  = lane + j * 32;
                    if (val > best || (val == best && id < bidx)) { best = val; bidx = id; }
                }
            }
            #pragma unroll
            for (int off = 16; off > 0; off >>= 1) {
                float ov = __shfl_xor_sync(0xffffffffu, best, off);
                int   oi = __shfl_xor_sync(0xffffffffu, bidx, off);
                if (ov > best || (ov == best && oi < bidx)) { best = ov; bidx = oi; }
            }
            topv[r] = best;
            topi[r] = bidx;
            if ((bidx & 31) == lane) used |= 1u << (bidx >> 5);
        }

        float sum = 0.f;
        #pragma unroll
        for (int r = 0; r < 8; ++r) sum += topv[r];
        float inv = 1.f / sum;

        if (lane == 0) {
            int gt = t0 + t;
            #pragma unroll
            for (int r = 0; r < 8; ++r)
                out[(size_t)gt * TOPK + r] = topv[r] * inv;
            if (write_idx) {
                #pragma unroll
                for (int r = 0; r < 8; ++r)
                    out[(size_t)TOKENS * TOPK + (size_t)gt * TOPK + r] = (float)topi[r];
            }
        }
    }
}

extern "C" void kernel_launch(void* const* d_in, const int* in_sizes, int n_in,
                              void* d_out, int out_size)
{
    const float* x = (const float*)d_in[0];   // [TOKENS, DIM]
    const float* w = (const float*)d_in[1];   // [NEXP, DIM]
    float* out = (float*)d_out;

    int write_idx = (out_size >= 2 * TOKENS * TOPK) ? 1 : 0;

    cudaFuncSetAttribute(gate_bf16x3_kernel, cudaFuncAttributeMaxDynamicSharedMemorySize, SMEM_BYTES);

    wsplit_kernel<<<(NEXP * NCH) / 256, 256>>>(w);
    gate_bf16x3_kernel<<<TOKENS / TM, NTH, SMEM_BYTES>>>(x, out, write_idx);
}